// round 4
// baseline (speedup 1.0000x reference)
#include <cuda_runtime.h>
#include <math.h>

#define Bn 256
#define Tn 512
#define Fn 16
#define Hn 256
#define Gn (4*Hn)   // 1024

// ---- scratch (__device__ globals; no allocation allowed) ----
__device__ float g_Wc0[(Fn+Hn)*Gn];   // [272][1024] combined transposed weights, layer 0
__device__ float g_Wc1[(Hn+Hn)*Gn];   // [512][1024] layer 1
__device__ float g_b0[Gn], g_b1[Gn];  // combined biases (b_ih + b_hh)
__device__ float g_h0out[(size_t)Bn*Tn*Hn];  // layer-0 hidden sequence [b][t][u]
__device__ float g_hlast[Bn*Hn];             // layer-1 h at t = len-1

// ---------------- packed f32x2 helpers ----------------
__device__ __forceinline__ unsigned long long pack2(float a, float b) {
    unsigned long long r;
    asm("mov.b64 %0, {%1, %2};" : "=l"(r) : "f"(a), "f"(b));
    return r;
}
__device__ __forceinline__ void unpack2(unsigned long long v, float& a, float& b) {
    asm("mov.b64 {%0, %1}, %2;" : "=f"(a), "=f"(b) : "l"(v));
}
__device__ __forceinline__ void ffma2(unsigned long long& acc, unsigned long long a,
                                      unsigned long long b) {
    asm("fma.rn.f32x2 %0, %1, %2, %0;" : "+l"(acc) : "l"(a), "l"(b));
}

__device__ __forceinline__ float fast_sigmoid(float x) {
    return 1.f / (1.f + __expf(-x));        // inf-safe at both ends
}
__device__ __forceinline__ float fast_tanh(float x) {
    return 1.f - 2.f / (1.f + __expf(2.f * x));  // inf-safe: ->1 / ->-1
}

// ---------------- weight prep: transpose + combine ----------------
__global__ void prep_kernel(const float* __restrict__ wih0, const float* __restrict__ whh0,
                            const float* __restrict__ bih0, const float* __restrict__ bhh0,
                            const float* __restrict__ wih1, const float* __restrict__ whh1,
                            const float* __restrict__ bih1, const float* __restrict__ bhh1) {
    int idx = blockIdx.x * blockDim.x + threadIdx.x;
    int stride = gridDim.x * blockDim.x;
    const int n0 = (Fn+Hn)*Gn;
    const int n1 = (Hn+Hn)*Gn;
    for (int i = idx; i < n0; i += stride) {
        int k = i >> 10, j = i & (Gn-1);
        g_Wc0[i] = (k < Fn) ? wih0[j*Fn + k] : whh0[j*Hn + (k - Fn)];
    }
    for (int i = idx; i < n1; i += stride) {
        int k = i >> 10, j = i & (Gn-1);
        g_Wc1[i] = (k < Hn) ? wih1[j*Hn + k] : whh1[j*Hn + (k - Hn)];
    }
    for (int i = idx; i < Gn; i += stride) {
        g_b0[i] = bih0[i] + bhh0[i];
        g_b1[i] = bih1[i] + bhh1[i];
    }
}

// ---------------- persistent per-layer LSTM kernel ----------------
// 256 threads/CTA, 4 batches/CTA, 64 CTAs.
// Gate phase: thread t owns 4 consecutive gate rows (j4=t*4) x 4 batches.
//   Weights via LDG.128 -> two packed (w_j,w_j+1) u64s directly feed FFMA2.
//   v kept in smem as pre-packed (v,v) u64, batch-major -> broadcast LDS.64.
// Update phase: thread t -> (b = t>>6, units uu+64i); c in 4 registers.
template<int KIN, int XDIM, int LAYER>
__global__ __launch_bounds__(256, 1)
void lstm_layer(const float* __restrict__ xin_ext, const int* __restrict__ lengths)
{
    __shared__ __align__(16) unsigned long long v2[4][KIN];  // (v,v) packed, batch-major
    __shared__ __align__(16) float g_sh[4][Gn];              // gate preactivations
    __shared__ int len_sh[4];

    const float* __restrict__ Wc   = (LAYER == 0) ? g_Wc0 : g_Wc1;
    const float* __restrict__ bias = (LAYER == 0) ? g_b0 : g_b1;

    const int t8 = threadIdx.x;       // 0..255
    const int j4 = t8 * 4;            // gate-phase: 4 consecutive gate rows
    const int b0 = blockIdx.x * 4;
    const int bb = t8 >> 6;           // update-phase batch
    const int uu = t8 & 63;           // update-phase base unit

    // zero v2, load lengths
    for (int i = t8; i < 4*KIN; i += 256) ((unsigned long long*)v2)[i] = 0ull;
    if (t8 < 4) len_sh[t8] = lengths[b0 + t8];

    // packed biases for rows j4..j4+3
    const float4 bv = *reinterpret_cast<const float4*>(&bias[j4]);
    const unsigned long long bias01 = pack2(bv.x, bv.y);
    const unsigned long long bias23 = pack2(bv.z, bv.w);

    float cc0 = 0.f, cc1 = 0.f, cc2 = 0.f, cc3 = 0.f;
    const float* wp = Wc + j4;

    // prologue: load x_0
    __syncthreads();
    if (XDIM == Fn) {
        if (t8 < 64) {
            int b = t8 >> 4, k = t8 & 15;
            float x = xin_ext[((size_t)(b0 + b) * Tn + 0) * Fn + k];
            v2[b][k] = pack2(x, x);
        }
    } else {
        #pragma unroll
        for (int i = 0; i < 4; ++i) {
            int k = uu + 64*i;
            float x = g_h0out[(size_t)(b0 + bb) * Tn * Hn + (size_t)0 * Hn + k];
            v2[bb][k] = pack2(x, x);
        }
    }
    __syncthreads();

    for (int t = 0; t < Tn; ++t) {
        // ---- gate phase: acc[b] = bias + Wc^T . v ----
        unsigned long long a00 = bias01, a01 = bias23;
        unsigned long long a10 = bias01, a11 = bias23;
        unsigned long long a20 = bias01, a21 = bias23;
        unsigned long long a30 = bias01, a31 = bias23;
        const float* wk = wp;
        #pragma unroll 4
        for (int k = 0; k < KIN; ++k) {
            ulonglong2 ww = *reinterpret_cast<const ulonglong2*>(wk);
            wk += Gn;
            unsigned long long vb0 = v2[0][k];
            unsigned long long vb1 = v2[1][k];
            unsigned long long vb2 = v2[2][k];
            unsigned long long vb3 = v2[3][k];
            ffma2(a00, ww.x, vb0); ffma2(a01, ww.y, vb0);
            ffma2(a10, ww.x, vb1); ffma2(a11, ww.y, vb1);
            ffma2(a20, ww.x, vb2); ffma2(a21, ww.y, vb2);
            ffma2(a30, ww.x, vb3); ffma2(a31, ww.y, vb3);
        }
        {
            float x0, x1, x2, x3;
            unpack2(a00, x0, x1); unpack2(a01, x2, x3);
            *reinterpret_cast<float4*>(&g_sh[0][j4]) = make_float4(x0, x1, x2, x3);
            unpack2(a10, x0, x1); unpack2(a11, x2, x3);
            *reinterpret_cast<float4*>(&g_sh[1][j4]) = make_float4(x0, x1, x2, x3);
            unpack2(a20, x0, x1); unpack2(a21, x2, x3);
            *reinterpret_cast<float4*>(&g_sh[2][j4]) = make_float4(x0, x1, x2, x3);
            unpack2(a30, x0, x1); unpack2(a31, x2, x3);
            *reinterpret_cast<float4*>(&g_sh[3][j4]) = make_float4(x0, x1, x2, x3);
        }
        __syncthreads();

        // ---- update phase (PyTorch gate order i,f,g,o) + x prefetch (t+1) ----
        {
            float* cptr[1]; (void)cptr;
            #pragma unroll
            for (int i = 0; i < 4; ++i) {
                int ui = uu + 64*i;
                float ig = g_sh[bb][ui];
                float fg = g_sh[bb][256 + ui];
                float gg = g_sh[bb][512 + ui];
                float og = g_sh[bb][768 + ui];
                float is = fast_sigmoid(ig);
                float fs = fast_sigmoid(fg);
                float os = fast_sigmoid(og);
                float gt = fast_tanh(gg);
                float c = (i == 0 ? cc0 : i == 1 ? cc1 : i == 2 ? cc2 : cc3);
                c = fs * c + is * gt;
                if (i == 0) cc0 = c; else if (i == 1) cc1 = c;
                else if (i == 2) cc2 = c; else cc3 = c;
                float h = os * fast_tanh(c);
                v2[bb][XDIM + ui] = pack2(h, h);
                if (LAYER == 0) {
                    g_h0out[(size_t)(b0 + bb) * Tn * Hn + (size_t)t * Hn + ui] = h;
                } else {
                    if (t == len_sh[bb] - 1) g_hlast[(b0 + bb) * Hn + ui] = h;
                }
            }
            // prefetch x_{t+1}
            if (t + 1 < Tn) {
                if (XDIM == Fn) {
                    if (t8 < 64) {
                        int b = t8 >> 4, k = t8 & 15;
                        float x = xin_ext[((size_t)(b0 + b) * Tn + (t+1)) * Fn + k];
                        v2[b][k] = pack2(x, x);
                    }
                } else {
                    #pragma unroll
                    for (int i = 0; i < 4; ++i) {
                        int k = uu + 64*i;
                        float x = g_h0out[(size_t)(b0 + bb) * Tn * Hn
                                          + (size_t)(t+1) * Hn + k];
                        v2[bb][k] = pack2(x, x);
                    }
                }
            }
        }
        __syncthreads();
    }
}

// ---------------- final: relu(hlast) @ fc_w^T + fc_b ----------------
__global__ void final_kernel(const float* __restrict__ fc_w, const float* __restrict__ fc_b,
                             float* __restrict__ out) {
    __shared__ float red[256];
    int b = blockIdx.x, u = threadIdx.x;
    float v = fmaxf(g_hlast[b * Hn + u], 0.f) * fc_w[u];
    red[u] = v;
    __syncthreads();
    #pragma unroll
    for (int s = 128; s > 0; s >>= 1) {
        if (u < s) red[u] += red[u + s];
        __syncthreads();
    }
    if (u == 0) out[b] = red[0] + fc_b[0];
}

extern "C" void kernel_launch(void* const* d_in, const int* in_sizes, int n_in,
                              void* d_out, int out_size) {
    const float* x    = (const float*)d_in[0];
    const int*   lens = (const int*)  d_in[1];
    const float* wih0 = (const float*)d_in[2];
    const float* whh0 = (const float*)d_in[3];
    const float* bih0 = (const float*)d_in[4];
    const float* bhh0 = (const float*)d_in[5];
    const float* wih1 = (const float*)d_in[6];
    const float* whh1 = (const float*)d_in[7];
    const float* bih1 = (const float*)d_in[8];
    const float* bhh1 = (const float*)d_in[9];
    const float* fcw  = (const float*)d_in[10];
    const float* fcb  = (const float*)d_in[11];
    float* out = (float*)d_out;

    prep_kernel<<<148, 256>>>(wih0, whh0, bih0, bhh0, wih1, whh1, bih1, bhh1);
    lstm_layer<Fn + Hn, Fn, 0><<<Bn / 4, 256>>>(x, lens);
    lstm_layer<Hn + Hn, Hn, 1><<<Bn / 4, 256>>>(nullptr, lens);
    final_kernel<<<Bn, 256>>>(fcw, fcb, out);
}

// round 5
// speedup vs baseline: 1.5110x; 1.5110x over previous
#include <cuda_runtime.h>
#include <math.h>

#define Bn 256
#define Tn 512
#define Fn 16
#define Hn 256
#define Gn (4*Hn)   // 1024
#define KPAD 16     // prefetch-overrun padding rows

// ---- scratch (__device__ globals; no allocation allowed) ----
__device__ float g_Wc0[(Fn+Hn+KPAD)*Gn];   // [272+pad][1024] transposed combined W, layer 0
__device__ float g_Wc1[(Hn+Hn+KPAD)*Gn];   // [512+pad][1024] layer 1
__device__ float g_b0[Gn], g_b1[Gn];       // combined biases (b_ih + b_hh)
__device__ float g_h0out[(size_t)Bn*Tn*Hn];  // layer-0 hidden sequence [b][t][u]
__device__ float g_hlast[Bn*Hn];             // layer-1 h at t = len-1

// ---------------- packed f32x2 helpers ----------------
__device__ __forceinline__ unsigned long long pack2(float a, float b) {
    unsigned long long r;
    asm("mov.b64 %0, {%1, %2};" : "=l"(r) : "f"(a), "f"(b));
    return r;
}
__device__ __forceinline__ void unpack2(unsigned long long v, float& a, float& b) {
    asm("mov.b64 {%0, %1}, %2;" : "=f"(a), "=f"(b) : "l"(v));
}
__device__ __forceinline__ void ffma2(unsigned long long& acc, unsigned long long a,
                                      unsigned long long b) {
    asm("fma.rn.f32x2 %0, %1, %2, %0;" : "+l"(acc) : "l"(a), "l"(b));
}

__device__ __forceinline__ float fast_sigmoid(float x) {
    return 1.f / (1.f + __expf(-x));             // inf-safe at both ends
}
__device__ __forceinline__ float fast_tanh(float x) {
    return 1.f - 2.f / (1.f + __expf(2.f * x));  // inf-safe: ->1 / ->-1
}

// ---------------- weight prep: transpose + combine ----------------
__global__ void prep_kernel(const float* __restrict__ wih0, const float* __restrict__ whh0,
                            const float* __restrict__ bih0, const float* __restrict__ bhh0,
                            const float* __restrict__ wih1, const float* __restrict__ whh1,
                            const float* __restrict__ bih1, const float* __restrict__ bhh1) {
    int idx = blockIdx.x * blockDim.x + threadIdx.x;
    int stride = gridDim.x * blockDim.x;
    const int n0 = (Fn+Hn)*Gn;
    const int n1 = (Hn+Hn)*Gn;
    for (int i = idx; i < n0; i += stride) {
        int k = i >> 10, j = i & (Gn-1);
        g_Wc0[i] = (k < Fn) ? wih0[j*Fn + k] : whh0[j*Hn + (k - Fn)];
    }
    for (int i = idx; i < n1; i += stride) {
        int k = i >> 10, j = i & (Gn-1);
        g_Wc1[i] = (k < Hn) ? wih1[j*Hn + k] : whh1[j*Hn + (k - Hn)];
    }
    for (int i = idx; i < Gn; i += stride) {
        g_b0[i] = bih0[i] + bhh0[i];
        g_b1[i] = bih1[i] + bhh1[i];
    }
}

// ---------------- persistent per-layer LSTM kernel ----------------
// 256 threads/CTA, 4 batches/CTA, 64 CTAs.
// Gate phase: thread t owns 4 consecutive gate rows (j4=t*4) x 4 batches.
//   Weight stream: LDG.128, 8-deep double-buffered register pipeline
//   (8 loads in flight while previous 8 compute) -> ~32KB in flight per SM.
//   v kept in smem as pre-packed (v,v) u64, k-major [k][4] -> 2 broadcast LDS.128/k.
// Update phase: thread t -> (b = t>>6, units uu+64i); c in 4 registers.
template<int KIN, int XDIM, int LAYER>
__global__ __launch_bounds__(256, 1)
void lstm_layer(const float* __restrict__ xin_ext, const int* __restrict__ lengths)
{
    __shared__ __align__(16) ulonglong2 v2s[KIN][2];  // per k: {(v0,v0),(v1,v1)},{(v2,v2),(v3,v3)}
    __shared__ __align__(16) float g_sh[4][Gn];       // gate preactivations
    __shared__ int len_sh[4];

    const float* __restrict__ Wc   = (LAYER == 0) ? g_Wc0 : g_Wc1;
    const float* __restrict__ bias = (LAYER == 0) ? g_b0 : g_b1;

    const int t8 = threadIdx.x;       // 0..255
    const int j4 = t8 * 4;            // gate-phase: 4 consecutive gate rows
    const int b0 = blockIdx.x * 4;
    const int bb = t8 >> 6;           // update-phase batch
    const int uu = t8 & 63;           // update-phase base unit

    unsigned long long* v2flat = reinterpret_cast<unsigned long long*>(v2s);

    // zero v2, load lengths
    for (int i = t8; i < 4*KIN; i += 256) v2flat[i] = 0ull;
    if (t8 < 4) len_sh[t8] = lengths[b0 + t8];

    // packed biases for rows j4..j4+3
    const float4 bv = *reinterpret_cast<const float4*>(&bias[j4]);
    const unsigned long long bias01 = pack2(bv.x, bv.y);
    const unsigned long long bias23 = pack2(bv.z, bv.w);

    float cc0 = 0.f, cc1 = 0.f, cc2 = 0.f, cc3 = 0.f;
    // weight base: ulonglong2 units; row k at offset k*256 + t8
    const ulonglong2* __restrict__ wbase =
        reinterpret_cast<const ulonglong2*>(Wc) + t8;

    // prologue: load x_0
    __syncthreads();
    if (XDIM == Fn) {
        if (t8 < 64) {
            int b = t8 >> 4, k = t8 & 15;
            float x = xin_ext[((size_t)(b0 + b) * Tn + 0) * Fn + k];
            v2flat[k*4 + b] = pack2(x, x);
        }
    } else {
        // thread loads float4 at k4 = uu*4 for batch bb
        const float4 xv = *reinterpret_cast<const float4*>(
            g_h0out + (size_t)(b0 + bb) * Tn * Hn + (size_t)uu * 4);
        int k4 = uu * 4;
        v2flat[(k4+0)*4 + bb] = pack2(xv.x, xv.x);
        v2flat[(k4+1)*4 + bb] = pack2(xv.y, xv.y);
        v2flat[(k4+2)*4 + bb] = pack2(xv.z, xv.z);
        v2flat[(k4+3)*4 + bb] = pack2(xv.w, xv.w);
    }
    __syncthreads();

    for (int t = 0; t < Tn; ++t) {
        // ---- gate phase: acc[b] = bias + Wc^T . v, 8-deep double-buffered ----
        unsigned long long a00 = bias01, a01 = bias23;
        unsigned long long a10 = bias01, a11 = bias23;
        unsigned long long a20 = bias01, a21 = bias23;
        unsigned long long a30 = bias01, a31 = bias23;

        ulonglong2 wA[8], wB[8];
        #pragma unroll
        for (int i = 0; i < 8; ++i) wA[i] = wbase[i * 256];

        #define GROUP(W, KB)                                                  \
            _Pragma("unroll")                                                 \
            for (int i = 0; i < 8; ++i) {                                     \
                ulonglong2 p = v2s[(KB) + i][0];                              \
                ulonglong2 q = v2s[(KB) + i][1];                              \
                ffma2(a00, W[i].x, p.x); ffma2(a01, W[i].y, p.x);             \
                ffma2(a10, W[i].x, p.y); ffma2(a11, W[i].y, p.y);             \
                ffma2(a20, W[i].x, q.x); ffma2(a21, W[i].y, q.x);             \
                ffma2(a30, W[i].x, q.y); ffma2(a31, W[i].y, q.y);             \
            }

        #pragma unroll 2
        for (int kk = 0; kk < KIN; kk += 16) {
            #pragma unroll
            for (int i = 0; i < 8; ++i) wB[i] = wbase[(kk + 8 + i) * 256];
            GROUP(wA, kk)
            #pragma unroll
            for (int i = 0; i < 8; ++i) wA[i] = wbase[(kk + 16 + i) * 256]; // last: pads
            GROUP(wB, kk + 8)
        }
        #undef GROUP

        {
            float x0, x1, x2, x3;
            unpack2(a00, x0, x1); unpack2(a01, x2, x3);
            *reinterpret_cast<float4*>(&g_sh[0][j4]) = make_float4(x0, x1, x2, x3);
            unpack2(a10, x0, x1); unpack2(a11, x2, x3);
            *reinterpret_cast<float4*>(&g_sh[1][j4]) = make_float4(x0, x1, x2, x3);
            unpack2(a20, x0, x1); unpack2(a21, x2, x3);
            *reinterpret_cast<float4*>(&g_sh[2][j4]) = make_float4(x0, x1, x2, x3);
            unpack2(a30, x0, x1); unpack2(a31, x2, x3);
            *reinterpret_cast<float4*>(&g_sh[3][j4]) = make_float4(x0, x1, x2, x3);
        }
        __syncthreads();

        // ---- update phase (PyTorch gate order i,f,g,o) + x prefetch (t+1) ----
        {
            #pragma unroll
            for (int i = 0; i < 4; ++i) {
                int ui = uu + 64*i;
                float ig = g_sh[bb][ui];
                float fg = g_sh[bb][256 + ui];
                float gg = g_sh[bb][512 + ui];
                float og = g_sh[bb][768 + ui];
                float is = fast_sigmoid(ig);
                float fs = fast_sigmoid(fg);
                float os = fast_sigmoid(og);
                float gt = fast_tanh(gg);
                float c = (i == 0 ? cc0 : i == 1 ? cc1 : i == 2 ? cc2 : cc3);
                c = fs * c + is * gt;
                if (i == 0) cc0 = c; else if (i == 1) cc1 = c;
                else if (i == 2) cc2 = c; else cc3 = c;
                float h = os * fast_tanh(c);
                v2flat[(XDIM + ui)*4 + bb] = pack2(h, h);
                if (LAYER == 0) {
                    g_h0out[(size_t)(b0 + bb) * Tn * Hn + (size_t)t * Hn + ui] = h;
                } else {
                    if (t == len_sh[bb] - 1) g_hlast[(b0 + bb) * Hn + ui] = h;
                }
            }
            // prefetch x_{t+1}
            if (t + 1 < Tn) {
                if (XDIM == Fn) {
                    if (t8 < 64) {
                        int b = t8 >> 4, k = t8 & 15;
                        float x = xin_ext[((size_t)(b0 + b) * Tn + (t+1)) * Fn + k];
                        v2flat[k*4 + b] = pack2(x, x);
                    }
                } else {
                    const float4 xv = *reinterpret_cast<const float4*>(
                        g_h0out + (size_t)(b0 + bb) * Tn * Hn
                                + (size_t)(t+1) * Hn + (size_t)uu * 4);
                    int k4 = uu * 4;
                    v2flat[(k4+0)*4 + bb] = pack2(xv.x, xv.x);
                    v2flat[(k4+1)*4 + bb] = pack2(xv.y, xv.y);
                    v2flat[(k4+2)*4 + bb] = pack2(xv.z, xv.z);
                    v2flat[(k4+3)*4 + bb] = pack2(xv.w, xv.w);
                }
            }
        }
        __syncthreads();
    }
}

// ---------------- final: relu(hlast) @ fc_w^T + fc_b ----------------
__global__ void final_kernel(const float* __restrict__ fc_w, const float* __restrict__ fc_b,
                             float* __restrict__ out) {
    __shared__ float red[256];
    int b = blockIdx.x, u = threadIdx.x;
    float v = fmaxf(g_hlast[b * Hn + u], 0.f) * fc_w[u];
    red[u] = v;
    __syncthreads();
    #pragma unroll
    for (int s = 128; s > 0; s >>= 1) {
        if (u < s) red[u] += red[u + s];
        __syncthreads();
    }
    if (u == 0) out[b] = red[0] + fc_b[0];
}

extern "C" void kernel_launch(void* const* d_in, const int* in_sizes, int n_in,
                              void* d_out, int out_size) {
    const float* x    = (const float*)d_in[0];
    const int*   lens = (const int*)  d_in[1];
    const float* wih0 = (const float*)d_in[2];
    const float* whh0 = (const float*)d_in[3];
    const float* bih0 = (const float*)d_in[4];
    const float* bhh0 = (const float*)d_in[5];
    const float* wih1 = (const float*)d_in[6];
    const float* whh1 = (const float*)d_in[7];
    const float* bih1 = (const float*)d_in[8];
    const float* bhh1 = (const float*)d_in[9];
    const float* fcw  = (const float*)d_in[10];
    const float* fcb  = (const float*)d_in[11];
    float* out = (float*)d_out;

    prep_kernel<<<148, 256>>>(wih0, whh0, bih0, bhh0, wih1, whh1, bih1, bhh1);
    lstm_layer<Fn + Hn, Fn, 0><<<Bn / 4, 256>>>(x, lens);
    lstm_layer<Hn + Hn, Hn, 1><<<Bn / 4, 256>>>(nullptr, lens);
    final_kernel<<<Bn, 256>>>(fcw, fcb, out);
}

// round 7
// speedup vs baseline: 1.8908x; 1.2514x over previous
#include <cuda_runtime.h>
#include <math.h>
#include <stdint.h>

#define Bn 256
#define Tn 512
#define Fn 16
#define Hn 256
#define Gn (4*Hn)        // 1024 gate rows
#define CLSZ 4           // CTAs per cluster (unit-split)
#define BT 8             // batches per cluster group
#define NGRP (Bn/BT)     // 32 groups
#define UPC (Hn/CLSZ)    // 64 units per CTA
#define SSZ 16           // k-rows per cp.async stage
#define NBUF 3           // stage ring depth

typedef unsigned long long u64;

// ---- scratch (__device__ globals; no allocation allowed) ----
// interleaved weights: [k][unit*4 + gate], gate order i,f,g,o
__device__ float g_Wc0[(Fn+Hn)*Gn];
__device__ float g_Wc1[(Hn+Hn)*Gn];
__device__ float g_b0[Gn], g_b1[Gn];            // interleaved combined biases
__device__ float g_h0out[(size_t)Bn*Tn*Hn];     // layer-0 hidden sequence [b][t][u]
__device__ float g_hlast[Bn*Hn];                // layer-1 h at t = len-1
// h exchange: [parity][group][unit][batch] packed (h,h)
__device__ u64 g_hex[2][NGRP][Hn][BT];

// ---------------- packed f32x2 helpers ----------------
__device__ __forceinline__ u64 pack2(float a, float b) {
    u64 r; asm("mov.b64 %0, {%1, %2};" : "=l"(r) : "f"(a), "f"(b)); return r;
}
__device__ __forceinline__ void unpack2(u64 v, float& a, float& b) {
    asm("mov.b64 {%0, %1}, %2;" : "=f"(a), "=f"(b) : "l"(v));
}
__device__ __forceinline__ void ffma2(u64& acc, u64 a, u64 b) {
    asm("fma.rn.f32x2 %0, %1, %2, %0;" : "+l"(acc) : "l"(a), "l"(b));
}
__device__ __forceinline__ float fast_sigmoid(float x) {
    return 1.f / (1.f + __expf(-x));
}
__device__ __forceinline__ float fast_tanh(float x) {
    return 1.f - 2.f / (1.f + __expf(2.f * x));
}
__device__ __forceinline__ uint32_t ctarank() {
    uint32_t r; asm("mov.u32 %0, %%cluster_ctarank;" : "=r"(r)); return r;
}
__device__ __forceinline__ void cluster_sync() {
    asm volatile("barrier.cluster.arrive.aligned;" ::: "memory");
    asm volatile("barrier.cluster.wait.aligned;"   ::: "memory");
}
__device__ __forceinline__ void cp16(uint32_t dst_smem, const void* src) {
    asm volatile("cp.async.cg.shared.global [%0], [%1], 16;"
                 :: "r"(dst_smem), "l"(src) : "memory");
}
__device__ __forceinline__ void cp_commit() {
    asm volatile("cp.async.commit_group;" ::: "memory");
}
template<int N> __device__ __forceinline__ void cp_wait() {
    asm volatile("cp.async.wait_group %0;" :: "n"(N) : "memory");
}

// ---------------- weight prep: transpose + interleave [k][u*4+g] ----------------
__global__ void prep_kernel(const float* __restrict__ wih0, const float* __restrict__ whh0,
                            const float* __restrict__ bih0, const float* __restrict__ bhh0,
                            const float* __restrict__ wih1, const float* __restrict__ whh1,
                            const float* __restrict__ bih1, const float* __restrict__ bhh1) {
    int idx = blockIdx.x * blockDim.x + threadIdx.x;
    int stride = gridDim.x * blockDim.x;
    const int n0 = (Fn+Hn)*Gn, n1 = (Hn+Hn)*Gn;
    for (int i = idx; i < n0; i += stride) {
        int k = i >> 10, col = i & 1023, u = col >> 2, g = col & 3;
        int jo = g*Hn + u;
        g_Wc0[i] = (k < Fn) ? wih0[jo*Fn + k] : whh0[jo*Hn + (k - Fn)];
    }
    for (int i = idx; i < n1; i += stride) {
        int k = i >> 10, col = i & 1023, u = col >> 2, g = col & 3;
        int jo = g*Hn + u;
        g_Wc1[i] = (k < Hn) ? wih1[jo*Hn + k] : whh1[jo*Hn + (k - Hn)];
    }
    for (int col = idx; col < Gn; col += stride) {
        int u = col >> 2, g = col & 3, jo = g*Hn + u;
        g_b0[col] = bih0[jo] + bhh0[jo];
        g_b1[col] = bih1[jo] + bhh1[jo];
    }
}

// ---------------- clustered LSTM layer ----------------
// 128 CTAs, cluster of 4. Group = blockIdx/4 owns 8 batches; CTA rank owns 64 units.
// Thread t: unit u = t>>2 (local), q = t&3 -> batches {2q, 2q+1}.
// Weights stream via 3-stage cp.async ring (warp self-copies its own 128B/k slice).
// Gates + cell update in the same thread (no smem roundtrip for gates).
// h exchanged across the cluster via g_hex[parity] + cluster.sync (CCTL.IVALL).
template<int KIN, int XDIM, int LAYER>
__global__ __launch_bounds__(256, 1) __cluster_dims__(CLSZ, 1, 1)
void lstm_layer(const float* __restrict__ xin, const int* __restrict__ lengths)
{
    extern __shared__ __align__(16) char smem[];
    u64*   v2  = reinterpret_cast<u64*>(smem);              // [KIN][BT] packed (v,v)
    float* wst = reinterpret_cast<float*>(smem + (size_t)KIN * BT * 8); // [NBUF][SSZ][256]
    __shared__ int len_sh[BT];

    const float* __restrict__ Wc   = LAYER ? g_Wc1 : g_Wc0;
    const float* __restrict__ bias = LAYER ? g_b1 : g_b0;

    const int tid  = threadIdx.x;
    const int u    = tid >> 2;          // local unit 0..63
    const int q    = tid & 3;           // batch pair 0..3
    const int wid  = tid >> 5, lane = tid & 31;
    const int grp  = blockIdx.x >> 2;
    const uint32_t rank = ctarank();
    const int b0g  = grp * BT;
    const int unit = (int)rank * UPC + u;     // global unit 0..255

    const u64 bias01 = *reinterpret_cast<const u64*>(bias + unit*4);
    const u64 bias23 = *reinterpret_cast<const u64*>(bias + unit*4 + 2);

    if (tid < BT) len_sh[tid] = lengths[b0g + tid];

    // zero h region of v2
    for (int i = tid; i < Hn*BT; i += 256) v2[(size_t)XDIM*BT + i] = 0ull;
    // x region for t = 0
    if (XDIM == Fn) {
        if (tid < Fn*BT) {
            int k = tid >> 3, b = tid & 7;
            float xv = xin[((size_t)(b0g + b) * Tn + 0) * Fn + k];
            v2[k*BT + b] = pack2(xv, xv);
        }
    } else {
        int k = tid;
        #pragma unroll
        for (int b = 0; b < BT; ++b) {
            float hv = g_h0out[((size_t)(b0g + b) * Tn + 0) * Hn + k];
            v2[k*BT + b] = pack2(hv, hv);
        }
    }
    __syncthreads();

    float c0 = 0.f, c1 = 0.f;
    constexpr int NST = KIN / SSZ;
    const uint32_t wst_s = (uint32_t)__cvta_generic_to_shared(wst);
    // per-lane cp.async chunk indices: c = lane + 32*j, j=0..3
    //   k_local = c>>3, ci = c&7; each warp copies its own 128B/k slice.
    int par = 0;

    for (int t = 0; t < Tn; ++t) {
        // ---- issue stages 0,1 ----
        #pragma unroll
        for (int s0 = 0; s0 < 2; ++s0) {
            #pragma unroll
            for (int j = 0; j < 4; ++j) {
                int c = lane + 32*j, kl = c >> 3, ci = c & 7;
                const float* src = Wc + (size_t)(s0*SSZ + kl) * Gn
                                   + rank*(UPC*4) + wid*32 + ci*4;
                cp16(wst_s + ((s0 % NBUF)*SSZ + kl)*1024 + wid*128 + ci*16, src);
            }
            cp_commit();
        }

        u64 a01_0 = bias01, a23_0 = bias23;
        u64 a01_1 = bias01, a23_1 = bias23;

        for (int s = 0; s < NST; ++s) {
            if (s + 2 < NST) {
                #pragma unroll
                for (int j = 0; j < 4; ++j) {
                    int c = lane + 32*j, kl = c >> 3, ci = c & 7;
                    const float* src = Wc + (size_t)((s+2)*SSZ + kl) * Gn
                                       + rank*(UPC*4) + wid*32 + ci*4;
                    cp16(wst_s + (((s+2) % NBUF)*SSZ + kl)*1024 + wid*128 + ci*16, src);
                }
                cp_commit();
                cp_wait<2>();
            } else if (s + 1 < NST) {
                cp_wait<1>();
            } else {
                cp_wait<0>();
            }
            __syncwarp();

            const int kk = s * SSZ;
            const float* wb = wst + (s % NBUF)*(SSZ*256) + u*4;
            #pragma unroll
            for (int kl = 0; kl < SSZ; ++kl) {
                const ulonglong2 w = *reinterpret_cast<const ulonglong2*>(wb + kl*256);
                const ulonglong2 p = *reinterpret_cast<const ulonglong2*>(
                                        v2 + (size_t)(kk + kl)*BT + q*2);
                ffma2(a01_0, w.x, p.x); ffma2(a23_0, w.y, p.x);
                ffma2(a01_1, w.x, p.y); ffma2(a23_1, w.y, p.y);
            }
        }

        // ---- update (in-register): gates (i,f) in a01, (g,o) in a23 ----
        {
            float ig, fg, gg, og, h0v, h1v;
            unpack2(a01_0, ig, fg); unpack2(a23_0, gg, og);
            c0 = fast_sigmoid(fg) * c0 + fast_sigmoid(ig) * fast_tanh(gg);
            h0v = fast_sigmoid(og) * fast_tanh(c0);
            unpack2(a01_1, ig, fg); unpack2(a23_1, gg, og);
            c1 = fast_sigmoid(fg) * c1 + fast_sigmoid(ig) * fast_tanh(gg);
            h1v = fast_sigmoid(og) * fast_tanh(c1);

            ulonglong2 hh; hh.x = pack2(h0v, h0v); hh.y = pack2(h1v, h1v);
            *reinterpret_cast<ulonglong2*>(&g_hex[par][grp][unit][2*q]) = hh;

            if (LAYER == 0) {
                g_h0out[((size_t)(b0g + 2*q)   * Tn + t) * Hn + unit] = h0v;
                g_h0out[((size_t)(b0g + 2*q+1) * Tn + t) * Hn + unit] = h1v;
            } else {
                if (t == len_sh[2*q]   - 1) g_hlast[(b0g + 2*q)  *Hn + unit] = h0v;
                if (t == len_sh[2*q+1] - 1) g_hlast[(b0g + 2*q+1)*Hn + unit] = h1v;
            }
        }

        // ---- cluster barrier: releases h writes, flushes L1 for fresh reads ----
        cluster_sync();

        if (t + 1 < Tn) {
            // reload full h (all 4 slices) from g_hex[par]
            {
                const ulonglong2* src = reinterpret_cast<const ulonglong2*>(
                                            &g_hex[par][grp][tid][0]);
                ulonglong2* dst = reinterpret_cast<ulonglong2*>(
                                            v2 + (size_t)(XDIM + tid)*BT);
                #pragma unroll
                for (int j = 0; j < 4; ++j) dst[j] = src[j];
            }
            // prefetch x_{t+1}
            if (XDIM == Fn) {
                if (tid < Fn*BT) {
                    int k = tid >> 3, b = tid & 7;
                    float xv = xin[((size_t)(b0g + b) * Tn + (t+1)) * Fn + k];
                    v2[k*BT + b] = pack2(xv, xv);
                }
            } else {
                int k = tid;
                #pragma unroll
                for (int b = 0; b < BT; ++b) {
                    float hv = g_h0out[((size_t)(b0g + b) * Tn + (t+1)) * Hn + k];
                    v2[k*BT + b] = pack2(hv, hv);
                }
            }
            __syncthreads();
        }
        par ^= 1;
    }
}

// ---------------- final: relu(hlast) @ fc_w^T + fc_b ----------------
__global__ void final_kernel(const float* __restrict__ fc_w, const float* __restrict__ fc_b,
                             float* __restrict__ out) {
    __shared__ float red[256];
    int b = blockIdx.x, u = threadIdx.x;
    float v = fmaxf(g_hlast[b * Hn + u], 0.f) * fc_w[u];
    red[u] = v;
    __syncthreads();
    #pragma unroll
    for (int s = 128; s > 0; s >>= 1) {
        if (u < s) red[u] += red[u + s];
        __syncthreads();
    }
    if (u == 0) out[b] = red[0] + fc_b[0];
}

extern "C" void kernel_launch(void* const* d_in, const int* in_sizes, int n_in,
                              void* d_out, int out_size) {
    const float* x    = (const float*)d_in[0];
    const int*   lens = (const int*)  d_in[1];
    const float* wih0 = (const float*)d_in[2];
    const float* whh0 = (const float*)d_in[3];
    const float* bih0 = (const float*)d_in[4];
    const float* bhh0 = (const float*)d_in[5];
    const float* wih1 = (const float*)d_in[6];
    const float* whh1 = (const float*)d_in[7];
    const float* bih1 = (const float*)d_in[8];
    const float* bhh1 = (const float*)d_in[9];
    const float* fcw  = (const float*)d_in[10];
    const float* fcb  = (const float*)d_in[11];
    float* out = (float*)d_out;

    const int smem0 = (Fn+Hn)*BT*8 + NBUF*SSZ*256*4;   // 17408 + 49152
    const int smem1 = (Hn+Hn)*BT*8 + NBUF*SSZ*256*4;   // 32768 + 49152
    cudaFuncSetAttribute(lstm_layer<Fn+Hn, Fn, 0>,
                         cudaFuncAttributeMaxDynamicSharedMemorySize, smem0);
    cudaFuncSetAttribute(lstm_layer<Hn+Hn, Hn, 1>,
                         cudaFuncAttributeMaxDynamicSharedMemorySize, smem1);

    prep_kernel<<<148, 256>>>(wih0, whh0, bih0, bhh0, wih1, whh1, bih1, bhh1);
    lstm_layer<Fn+Hn, Fn, 0><<<NGRP*CLSZ, 256, smem0>>>(x, lens);
    lstm_layer<Hn+Hn, Hn, 1><<<NGRP*CLSZ, 256, smem1>>>(nullptr, lens);
    final_kernel<<<Bn, 256>>>(fcw, fcb, out);
}